// round 1
// baseline (speedup 1.0000x reference)
#include <cuda_runtime.h>
#include <stdint.h>

// Batched upper-triangular scatter:
//   out[b, r, c] = in[b, r*M - r*(r-1)/2 + (c-r)]  if c >= r
//                = 0                               otherwise
// M = 1024, TRIU = M*(M+1)/2 = 524800, B = 128.
//
// Pure bandwidth kernel: 256 MiB read + 512 MiB write.
// One block per (row, batch): 256 threads x float4 = 1024 columns.

#define MAT_M 1024
#define TRIU_LEN 524800

__global__ void __launch_bounds__(256, 8)
triu_scatter_kernel(const float* __restrict__ in, float* __restrict__ out)
{
    const int r  = blockIdx.x;            // 0..1023
    const int b  = blockIdx.y;            // 0..B-1
    const int c0 = threadIdx.x << 2;      // 0,4,...,1020

    // Start of row r inside the packed upper-triangular vector.
    // rowstart = r*M - r*(r-1)/2   (fits easily in 32-bit: max 524799)
    const int rowstart = r * MAT_M - ((r * (r - 1)) >> 1);

    const float* __restrict__ inb = in + (size_t)b * TRIU_LEN;

    float4 v;
    if (c0 >= r) {
        // Fully inside the upper triangle: contiguous packed load.
        const int off = rowstart + (c0 - r);
        v.x = __ldg(inb + off + 0);
        v.y = __ldg(inb + off + 1);
        v.z = __ldg(inb + off + 2);
        v.w = __ldg(inb + off + 3);
    } else if (c0 + 3 < r) {
        // Fully below the diagonal: pure zero store (no read traffic).
        v = make_float4(0.f, 0.f, 0.f, 0.f);
    } else {
        // Straddles the diagonal (at most one thread per row).
        float t[4];
        #pragma unroll
        for (int j = 0; j < 4; ++j) {
            const int c = c0 + j;
            t[j] = (c >= r) ? __ldg(inb + rowstart + (c - r)) : 0.f;
        }
        v = make_float4(t[0], t[1], t[2], t[3]);
    }

    // Output row-major: perfectly aligned 16B store.
    const size_t out_off = (((size_t)b * MAT_M + (size_t)r) * MAT_M) + (size_t)c0;
    *reinterpret_cast<float4*>(out + out_off) = v;
}

extern "C" void kernel_launch(void* const* d_in, const int* in_sizes, int n_in,
                              void* d_out, int out_size)
{
    const float* in = (const float*)d_in[0];
    float* out = (float*)d_out;

    const int B = in_sizes[0] / TRIU_LEN;   // 128 for the bench shape

    dim3 grid(MAT_M, B);
    dim3 block(256);
    triu_scatter_kernel<<<grid, block>>>(in, out);
}

// round 2
// speedup vs baseline: 1.0058x; 1.0058x over previous
#include <cuda_runtime.h>
#include <stdint.h>

// Batched upper-triangular scatter:
//   out[b, r, c] = in[b, r*M - r*(r-1)/2 + (c-r)]  if c >= r, else 0
// M = 1024, TRIU = 524800, B = 128.
//
// Pure bandwidth kernel: 256 MiB read + 512 MiB write (both mandatory).
// R1: 4 rows per block -> each thread front-batches 4 independent float4
// loads (MLP=4) before storing; streaming ld/st hints (single-use data).

#define MAT_M 1024
#define TRIU_LEN 524800
#define ROWS_PER_BLK 4

__device__ __forceinline__ float4 ldcs4(const float* p) {
    float4 v;
    v.x = __ldcs(p + 0);
    v.y = __ldcs(p + 1);
    v.z = __ldcs(p + 2);
    v.w = __ldcs(p + 3);
    return v;
}

__global__ void __launch_bounds__(256, 8)
triu_scatter_kernel(const float* __restrict__ in, float* __restrict__ out)
{
    const int r0 = blockIdx.x * ROWS_PER_BLK;   // 0,4,...,1020
    const int b  = blockIdx.y;                  // 0..B-1
    const int c0 = threadIdx.x << 2;            // 0,4,...,1020

    const float* __restrict__ inb = in + (size_t)b * TRIU_LEN;

    float4 v[ROWS_PER_BLK];

    // ---- Phase 1: batch all loads (independent -> MLP=4) ----
    #pragma unroll
    for (int j = 0; j < ROWS_PER_BLK; ++j) {
        const int r = r0 + j;
        // rowstart = r*M - r*(r-1)/2, max 524799 (fits int)
        const int rowstart = r * MAT_M - ((r * (r - 1)) >> 1);

        if (c0 >= r) {
            // Fully inside upper triangle: contiguous packed load.
            v[j] = ldcs4(inb + rowstart + (c0 - r));
        } else if (c0 + 3 < r) {
            // Fully below diagonal: pure zero store, no read.
            v[j] = make_float4(0.f, 0.f, 0.f, 0.f);
        } else {
            // Straddles the diagonal (<=1 thread per row).
            float t[4];
            #pragma unroll
            for (int k = 0; k < 4; ++k) {
                const int c = c0 + k;
                t[k] = (c >= r) ? __ldcs(inb + rowstart + (c - r)) : 0.f;
            }
            v[j] = make_float4(t[0], t[1], t[2], t[3]);
        }
    }

    // ---- Phase 2: aligned streaming float4 stores ----
    const size_t base = (((size_t)b * MAT_M + (size_t)r0) * MAT_M) + (size_t)c0;
    #pragma unroll
    for (int j = 0; j < ROWS_PER_BLK; ++j) {
        __stcs(reinterpret_cast<float4*>(out + base + (size_t)j * MAT_M), v[j]);
    }
}

extern "C" void kernel_launch(void* const* d_in, const int* in_sizes, int n_in,
                              void* d_out, int out_size)
{
    const float* in = (const float*)d_in[0];
    float* out = (float*)d_out;

    const int B = in_sizes[0] / TRIU_LEN;   // 128 for the bench shape

    dim3 grid(MAT_M / ROWS_PER_BLK, B);
    dim3 block(256);
    triu_scatter_kernel<<<grid, block>>>(in, out);
}